// round 4
// baseline (speedup 1.0000x reference)
#include <cuda_runtime.h>
#include <cuda_bf16.h>
#include <float.h>

// Problem constants
#define BATCH 4
#define SLEN  32768
#define C1    128
#define L1V   16384
#define C2    256
#define L2V   8192
#define HID   512
#define L3V   4096
#define VOCAB 2048
#define KCB   4

#define MARGIN 0.02f

typedef unsigned long long u64;
typedef unsigned int u32;

// Packed dual-fp32 FMA (kept for convs)
__device__ __forceinline__ u64 ffma2(u64 a, u64 b, u64 c) {
    u64 d;
    asm("fma.rn.f32x2 %0, %1, %2, %3;" : "=l"(d) : "l"(a), "l"(b), "l"(c));
    return d;
}
__device__ __forceinline__ u64 pack2(float x, float y) {
    u64 d;
    asm("mov.b64 %0, {%1, %2};" : "=l"(d) : "f"(x), "f"(y));
    return d;
}
__device__ __forceinline__ float2 unpack2(u64 d) {
    float2 r;
    asm("mov.b64 {%0, %1}, %2;" : "=f"(r.x), "=f"(r.y) : "l"(d));
    return r;
}
__device__ __forceinline__ u32 tf32_of(float x) {
    u32 r;
    asm("cvt.rna.tf32.f32 %0, %1;" : "=r"(r) : "f"(x));
    return r;
}
// m16n8k8 TF32 MMA, D += A*B
__device__ __forceinline__ void mma8(float* d, const u32* a, u32 b0, u32 b1) {
    asm("mma.sync.aligned.m16n8k8.row.col.f32.tf32.tf32.f32 "
        "{%0,%1,%2,%3},{%4,%5,%6,%7},{%8,%9},{%0,%1,%2,%3};"
        : "+f"(d[0]), "+f"(d[1]), "+f"(d[2]), "+f"(d[3])
        : "r"(a[0]), "r"(a[1]), "r"(a[2]), "r"(a[3]), "r"(b0), "r"(b1));
}

// Scratch
__device__ float g_y1[BATCH * C1 * L1V];
__device__ float g_y2[BATCH * C2 * L2V];
__device__ float g_y3[BATCH * HID * L3V];    // feats exact, [b][h][l]
__device__ float g_fhi[BATCH * HID * L3V];   // tf32 hi plane
__device__ float g_flo[BATCH * HID * L3V];   // tf32 lo plane
__device__ float g_chi[KCB * VOCAB * HID];   // codebook hi, [k][v][h]
__device__ float g_clo[KCB * VOCAB * HID];
__device__ float g_c2[KCB * VOCAB];
__device__ int   g_tok[BATCH * KCB * L3V];
__device__ int   g_list[BATCH * KCB * L3V];
__device__ int   g_cnt;

// ---------------------------------------------------------------------------
// conv1
// ---------------------------------------------------------------------------
__global__ void conv1_k(const float* __restrict__ a,
                        const float* __restrict__ w,
                        const float* __restrict__ bias) {
    int idx = blockIdx.x * blockDim.x + threadIdx.x;
    int l = idx & (L1V - 1);
    int c = (idx >> 14) & (C1 - 1);
    int b = idx >> 21;
    const float* ab = a + (size_t)b * SLEN;
    int p0 = 2 * l - 3;
    float acc = bias[c];
#pragma unroll
    for (int t = 0; t < 7; t++) {
        int p = p0 + t;
        float xv = (p >= 0 && p < SLEN) ? __ldg(&ab[p]) : 0.f;
        acc = fmaf(__ldg(&w[c * 7 + t]), xv, acc);
    }
    g_y1[idx] = fmaxf(acc, 0.f);
}

// ---------------------------------------------------------------------------
// conv2/conv3 (FFMA2 implicit GEMM). S3 also emits tf32 hi/lo planes.
// ---------------------------------------------------------------------------
template<int CI, int LIN, int CO, bool RELU, bool S3>
__global__ __launch_bounds__(256) void conv_k(const float* __restrict__ w,
                                              const float* __restrict__ bias) {
    constexpr int LOUT = LIN / 2;
    constexpr int CK = 8;
    __shared__ __align__(16) float xs[CK][136];
    __shared__ __align__(16) float ws[CK][7][68];

    const float* x = S3 ? g_y2 : g_y1;
    float* y       = S3 ? g_y3 : g_y2;

    int tid = threadIdx.x;
    int tx = tid & 15;
    int ty = tid >> 4;
    int l0 = blockIdx.x * 64;
    int co0 = blockIdx.y * 64;
    int b = blockIdx.z;
    const float* xb = x + (size_t)b * CI * LIN;
    int base = 2 * l0 - 3;

    u64 accA[4], accB[4];
#pragma unroll
    for (int i = 0; i < 4; i++) { accA[i] = 0ull; accB[i] = 0ull; }

    for (int ci0 = 0; ci0 < CI; ci0 += CK) {
        __syncthreads();
        for (int i = tid; i < CK * 134; i += 256) {
            int ci = i / 134;
            int p = i - ci * 134;
            int gp = base + p;
            float v = (gp >= 0 && gp < LIN) ? xb[(size_t)(ci0 + ci) * LIN + gp] : 0.f;
            xs[ci][p] = v;
        }
        for (int i = tid; i < 64 * 56; i += 256) {
            int co = i / 56;
            int r = i - co * 56;
            int ci = r / 7;
            int t = r - ci * 7;
            ws[ci][t][co] = w[((size_t)(co0 + co) * CI + ci0 + ci) * 7 + t];
        }
        __syncthreads();

#pragma unroll
        for (int ci = 0; ci < CK; ci++) {
            float xr[13];
            float4 xa = *(const float4*)&xs[ci][8 * tx];
            float4 xb4 = *(const float4*)&xs[ci][8 * tx + 4];
            float4 xc = *(const float4*)&xs[ci][8 * tx + 8];
            xr[0] = xa.x;  xr[1] = xa.y;  xr[2] = xa.z;  xr[3] = xa.w;
            xr[4] = xb4.x; xr[5] = xb4.y; xr[6] = xb4.z; xr[7] = xb4.w;
            xr[8] = xc.x;  xr[9] = xc.y;  xr[10] = xc.z; xr[11] = xc.w;
            xr[12] = xs[ci][8 * tx + 12];
            u64 xd[13];
#pragma unroll
            for (int p = 0; p < 13; p++) xd[p] = pack2(xr[p], xr[p]);
#pragma unroll
            for (int t = 0; t < 7; t++) {
                const u64* wp = (const u64*)&ws[ci][t][ty * 4];
                u64 w01 = wp[0];
                u64 w23 = wp[1];
#pragma unroll
                for (int i = 0; i < 4; i++) {
                    u64 xv = xd[2 * i + t];
                    accA[i] = ffma2(w01, xv, accA[i]);
                    accB[i] = ffma2(w23, xv, accB[i]);
                }
            }
        }
    }
    float bv0 = bias[co0 + ty * 4 + 0];
    float bv1 = bias[co0 + ty * 4 + 1];
    float bv2 = bias[co0 + ty * 4 + 2];
    float bv3 = bias[co0 + ty * 4 + 3];
#pragma unroll
    for (int i = 0; i < 4; i++) {
        float2 a2 = unpack2(accA[i]);
        float2 b2 = unpack2(accB[i]);
        float vv[4] = {a2.x + bv0, a2.y + bv1, b2.x + bv2, b2.y + bv3};
        int lo = l0 + tx * 4 + i;
#pragma unroll
        for (int j = 0; j < 4; j++) {
            float v = vv[j];
            if (RELU) v = fmaxf(v, 0.f);
            size_t o = ((size_t)b * CO + co0 + ty * 4 + j) * LOUT + lo;
            y[o] = v;
            if (S3) {
                float hi = __uint_as_float(tf32_of(v));
                float lo2 = __uint_as_float(tf32_of(v - hi));
                g_fhi[o] = hi;
                g_flo[o] = lo2;
            }
        }
    }
}

// ---------------------------------------------------------------------------
// c2 + codebook tf32 split + counter reset. One warp per (k,v) row.
// ---------------------------------------------------------------------------
__global__ void c2_k(const float* __restrict__ cb) {
    if (blockIdx.x == 0 && threadIdx.x == 0) g_cnt = 0;
    int row = blockIdx.x * 8 + (threadIdx.x >> 5);
    int lane = threadIdx.x & 31;
    const float* r = cb + (size_t)row * HID;
    float s = 0.f;
    for (int h = lane * 4; h < HID; h += 128) {
        float4 v = *(const float4*)&r[h];
        s = fmaf(v.x, v.x, s); s = fmaf(v.y, v.y, s);
        s = fmaf(v.z, v.z, s); s = fmaf(v.w, v.w, s);
        float4 hi, lo;
        hi.x = __uint_as_float(tf32_of(v.x)); lo.x = __uint_as_float(tf32_of(v.x - hi.x));
        hi.y = __uint_as_float(tf32_of(v.y)); lo.y = __uint_as_float(tf32_of(v.y - hi.y));
        hi.z = __uint_as_float(tf32_of(v.z)); lo.z = __uint_as_float(tf32_of(v.z - hi.z));
        hi.w = __uint_as_float(tf32_of(v.w)); lo.w = __uint_as_float(tf32_of(v.w - hi.w));
        *(float4*)&g_chi[(size_t)row * HID + h] = hi;
        *(float4*)&g_clo[(size_t)row * HID + h] = lo;
    }
#pragma unroll
    for (int o = 16; o; o >>= 1) s += __shfl_xor_sync(0xFFFFFFFFu, s, o);
    if (!lane) g_c2[row] = s;
}

// ---------------------------------------------------------------------------
// dist: 3xTF32 tensor-core cross GEMM + fused top-2 argmin.
// Grid (L3/128, KCB, BATCH), 256 thr = 8 warps (4 l-warps x 2 v-warps).
// Warp tile 32l x 64v; mma m16n8k8; acc[2 m][8 n][4].
// ---------------------------------------------------------------------------
__global__ __launch_bounds__(256, 2) void dist_k(float* __restrict__ out_tok) {
    __shared__ __align__(16) float as_hi[8][132], as_lo[8][132];
    __shared__ __align__(16) float bs_hi[8][132], bs_lo[8][132];
    __shared__ float c2s[128];
    __shared__ float rv1[128][8], rv2[128][8];
    __shared__ int   ri1[128][8];

    int tid = threadIdx.x;
    int wid = tid >> 5, lane = tid & 31;
    int grp = lane >> 2, tig = lane & 3;
    int wm = wid & 3, wn = wid >> 2;
    int l0 = blockIdx.x * 128;
    int k = blockIdx.y;
    int b = blockIdx.z;

    const float* fhi = g_fhi + (size_t)b * HID * L3V;
    const float* flo = g_flo + (size_t)b * HID * L3V;
    const float* chi = g_chi + (size_t)k * VOCAB * HID;
    const float* clo = g_clo + (size_t)k * VOCAB * HID;

    // top-2 per l handled by this thread: li = mi*2 + half
    float t1[4], t2[4];
    int ti1[4];
#pragma unroll
    for (int i = 0; i < 4; i++) { t1[i] = FLT_MAX; t2[i] = FLT_MAX; ti1[i] = 0; }

    int skk = tid >> 5;            // staging: plane row
    int sl  = (tid & 31) * 4;      // staging: l offset
    int svv = tid >> 1;            // staging B: v row
    int shf = (tid & 1) * 4;       // staging B: h half

    for (int v0 = 0; v0 < VOCAB; v0 += 128) {
        __syncthreads();
        if (tid < 128) c2s[tid] = g_c2[k * VOCAB + v0 + tid];

        float acc[2][8][4];
#pragma unroll
        for (int mi = 0; mi < 2; mi++)
#pragma unroll
            for (int j = 0; j < 8; j++)
#pragma unroll
                for (int e = 0; e < 4; e++) acc[mi][j][e] = 0.f;

        for (int ht = 0; ht < HID; ht += 8) {
            __syncthreads();
            // stage A: as[kk][l] (coalesced)
            *(float4*)&as_hi[skk][sl] = *(const float4*)&fhi[(size_t)(ht + skk) * L3V + l0 + sl];
            *(float4*)&as_lo[skk][sl] = *(const float4*)&flo[(size_t)(ht + skk) * L3V + l0 + sl];
            // stage B: bs[kk][v] (transpose)
            {
                float4 h4 = *(const float4*)&chi[(size_t)(v0 + svv) * HID + ht + shf];
                bs_hi[shf + 0][svv] = h4.x; bs_hi[shf + 1][svv] = h4.y;
                bs_hi[shf + 2][svv] = h4.z; bs_hi[shf + 3][svv] = h4.w;
                float4 l4 = *(const float4*)&clo[(size_t)(v0 + svv) * HID + ht + shf];
                bs_lo[shf + 0][svv] = l4.x; bs_lo[shf + 1][svv] = l4.y;
                bs_lo[shf + 2][svv] = l4.z; bs_lo[shf + 3][svv] = l4.w;
            }
            __syncthreads();

            u32 ah[2][4], al[2][4];
#pragma unroll
            for (int mi = 0; mi < 2; mi++) {
                int lb = wm * 32 + mi * 16;
                ah[mi][0] = __float_as_uint(as_hi[tig][lb + grp]);
                ah[mi][1] = __float_as_uint(as_hi[tig][lb + grp + 8]);
                ah[mi][2] = __float_as_uint(as_hi[tig + 4][lb + grp]);
                ah[mi][3] = __float_as_uint(as_hi[tig + 4][lb + grp + 8]);
                al[mi][0] = __float_as_uint(as_lo[tig][lb + grp]);
                al[mi][1] = __float_as_uint(as_lo[tig][lb + grp + 8]);
                al[mi][2] = __float_as_uint(as_lo[tig + 4][lb + grp]);
                al[mi][3] = __float_as_uint(as_lo[tig + 4][lb + grp + 8]);
            }
#pragma unroll
            for (int j = 0; j < 8; j++) {
                int vb = wn * 64 + j * 8 + grp;
                u32 bh0 = __float_as_uint(bs_hi[tig][vb]);
                u32 bh1 = __float_as_uint(bs_hi[tig + 4][vb]);
                u32 bl0 = __float_as_uint(bs_lo[tig][vb]);
                u32 bl1 = __float_as_uint(bs_lo[tig + 4][vb]);
#pragma unroll
                for (int mi = 0; mi < 2; mi++) {
                    mma8(acc[mi][j], ah[mi], bh0, bh1);   // hi*hi
                    mma8(acc[mi][j], al[mi], bh0, bh1);   // lo*hi
                    mma8(acc[mi][j], ah[mi], bl0, bl1);   // hi*lo
                }
            }
        }
        // epilogue: d = c2 - 2*cross, running top-2 (v visited ascending)
#pragma unroll
        for (int mi = 0; mi < 2; mi++)
#pragma unroll
            for (int e = 0; e < 4; e++) {
                int li = mi * 2 + (e >> 1);
#pragma unroll
                for (int j = 0; j < 8; j++) {
                    int vloc = wn * 64 + j * 8 + 2 * tig + (e & 1);
                    float d = fmaf(-2.f, acc[mi][j][e], c2s[vloc]);
                    if (d < t1[li]) { t2[li] = t1[li]; t1[li] = d; ti1[li] = v0 + vloc; }
                    else if (d < t2[li]) t2[li] = d;
                }
            }
    }

    // reduction: 8 slots per l
#pragma unroll
    for (int mi = 0; mi < 2; mi++)
#pragma unroll
        for (int half = 0; half < 2; half++) {
            int li = mi * 2 + half;
            int l_loc = wm * 32 + mi * 16 + half * 8 + grp;
            int slot = tig * 2 + wn;
            rv1[l_loc][slot] = t1[li];
            ri1[l_loc][slot] = ti1[li];
            rv2[l_loc][slot] = t2[li];
        }
    __syncthreads();
    if (tid < 128) {
        int l = tid;
        float b1 = rv1[l][0], b2 = rv2[l][0];
        int bi = ri1[l][0];
#pragma unroll
        for (int s = 1; s < 8; s++) {
            float v1 = rv1[l][s], v2 = rv2[l][s];
            int i1 = ri1[l][s];
            if (v1 < b1 || (v1 == b1 && i1 < bi)) {
                b2 = fminf(fminf(b2, b1), v2);
                b1 = v1; bi = i1;
            } else {
                b2 = fminf(b2, v1);
            }
        }
        size_t o = ((size_t)b * KCB + k) * L3V + l0 + l;
        out_tok[o] = (float)bi;
        g_tok[o] = bi;
        if (b2 - b1 < MARGIN) {
            int pos = atomicAdd(&g_cnt, 1);
            g_list[pos] = (int)o;
        }
    }
}

// ---------------------------------------------------------------------------
// rescue: exact fp32 re-score of flagged tokens over all 2048 codewords.
// ---------------------------------------------------------------------------
__global__ __launch_bounds__(256) void rescue_k(const float* __restrict__ cb,
                                                float* __restrict__ out_tok) {
    __shared__ float ff[HID];
    __shared__ float bval[256];
    __shared__ int   bidx[256];
    int tid = threadIdx.x;
    int n = g_cnt;
    for (int it = blockIdx.x; it < n; it += gridDim.x) {
        int code = g_list[it];
        int l = code & (L3V - 1);
        int k = (code >> 12) & (KCB - 1);
        int b = code >> 14;
        __syncthreads();
        ff[tid] = g_y3[((size_t)b * HID + tid) * L3V + l];
        ff[tid + 256] = g_y3[((size_t)b * HID + tid + 256) * L3V + l];
        __syncthreads();
        const float* cbk = cb + (size_t)k * VOCAB * HID;
        float best = FLT_MAX;
        int besti = 0;
        for (int vi = 0; vi < 8; vi++) {
            int v = tid * 8 + vi;
            const float* r = cbk + (size_t)v * HID;
            float s = 0.f;
            for (int h = 0; h < HID; h += 4) {
                float4 c4 = *(const float4*)&r[h];
                s = fmaf(ff[h], c4.x, s);
                s = fmaf(ff[h + 1], c4.y, s);
                s = fmaf(ff[h + 2], c4.z, s);
                s = fmaf(ff[h + 3], c4.w, s);
            }
            float d = fmaf(-2.f, s, g_c2[k * VOCAB + v]);
            if (d < best) { best = d; besti = v; }
        }
        bval[tid] = best;
        bidx[tid] = besti;
        __syncthreads();
        if (tid == 0) {
            float bv = bval[0];
            int bi = bidx[0];
            for (int t = 1; t < 256; t++) {
                float v = bval[t];
                int ix = bidx[t];
                if (v < bv || (v == bv && ix < bi)) { bv = v; bi = ix; }
            }
            out_tok[code] = (float)bi;
            g_tok[code] = bi;
        }
    }
}

// ---------------------------------------------------------------------------
// emb
// ---------------------------------------------------------------------------
__global__ void emb_k(const float* __restrict__ E, float* __restrict__ out) {
    int pos = blockIdx.x;
    int b = pos >> 12;
    int l = pos & (L3V - 1);
    int t0 = g_tok[((size_t)b * KCB + 0) * L3V + l];
    int t1 = g_tok[((size_t)b * KCB + 1) * L3V + l];
    int t2 = g_tok[((size_t)b * KCB + 2) * L3V + l];
    int t3 = g_tok[((size_t)b * KCB + 3) * L3V + l];
    int h = threadIdx.x;
    float4 a = ((const float4*)(E + (size_t)t0 * HID))[h];
    float4 b4 = ((const float4*)(E + (size_t)t1 * HID))[h];
    float4 c = ((const float4*)(E + (size_t)t2 * HID))[h];
    float4 d = ((const float4*)(E + (size_t)t3 * HID))[h];
    float4 r;
    r.x = 0.25f * (a.x + b4.x + c.x + d.x);
    r.y = 0.25f * (a.y + b4.y + c.y + d.y);
    r.z = 0.25f * (a.z + b4.z + c.z + d.z);
    r.w = 0.25f * (a.w + b4.w + c.w + d.w);
    ((float4*)(out + (size_t)pos * HID))[h] = r;
}

// ---------------------------------------------------------------------------
extern "C" void kernel_launch(void* const* d_in, const int* in_sizes, int n_in,
                              void* d_out, int out_size) {
    const float* audio     = (const float*)d_in[0];
    const float* w1        = (const float*)d_in[1];
    const float* b1        = (const float*)d_in[2];
    const float* w2        = (const float*)d_in[3];
    const float* b2        = (const float*)d_in[4];
    const float* w3        = (const float*)d_in[5];
    const float* b3        = (const float*)d_in[6];
    const float* codebook  = (const float*)d_in[7];
    const float* embedding = (const float*)d_in[8];

    float* out_tok = (float*)d_out;
    float* out_emb = out_tok + (size_t)BATCH * KCB * L3V;

    conv1_k<<<(BATCH * C1 * L1V) / 256, 256>>>(audio, w1, b1);
    conv_k<C1, L1V, C2, true,  false><<<dim3(L2V / 64, C2 / 64, BATCH), 256>>>(w2, b2);
    conv_k<C2, L2V, HID, false, true ><<<dim3(L3V / 64, HID / 64, BATCH), 256>>>(w3, b3);
    c2_k<<<(KCB * VOCAB) / 8, 256>>>(codebook);
    dist_k<<<dim3(L3V / 128, KCB, BATCH), 256>>>(out_tok);
    rescue_k<<<512, 256>>>(codebook, out_tok);
    emb_k<<<BATCH * L3V, 128>>>(embedding, out_emb);
}